// round 3
// baseline (speedup 1.0000x reference)
#include <cuda_runtime.h>
#include <math.h>

#define T    2048
#define Dm   1024
#define E    8
#define FFm  4096
#define TOPK 2
#define NPAIR (T * TOPK)

// ---------------- scratch (__device__ globals: allocation-free) ----------------
__device__ int   g_count[E];
__device__ int   g_base[E];
__device__ int   g_tok[E * T];      // token id per (expert, pos)
__device__ float g_wt[E * T];       // routing weight per (expert, pos)
__device__ float g_inter[(size_t)NPAIR * FFm];   // 64 MB compact intermediate
__device__ float g_logits_fb[T * E];             // fallback if out buffer too small

// ---------------- kernel 0: reset counters (graph replays need idempotence) ----
__global__ void zero_counts_kernel() {
    if (threadIdx.x < E) g_count[threadIdx.x] = 0;
}

// ---------------- kernel 1: router (1 warp per token) ---------------------------
__global__ void router_kernel(const float* __restrict__ h,
                              const float* __restrict__ gw,
                              float* __restrict__ logits_out) {
    int warp = (blockIdx.x * blockDim.x + threadIdx.x) >> 5;
    int lane = threadIdx.x & 31;
    if (warp >= T) return;
    int t = warp;

    float acc[E];
#pragma unroll
    for (int e = 0; e < E; e++) acc[e] = 0.f;

    const float* hp = h + (size_t)t * Dm;
    for (int j = lane; j < Dm; j += 32) {
        float x = hp[j];
#pragma unroll
        for (int e = 0; e < E; e++) acc[e] += x * gw[e * Dm + j];
    }
#pragma unroll
    for (int e = 0; e < E; e++) {
#pragma unroll
        for (int o = 16; o; o >>= 1) acc[e] += __shfl_xor_sync(0xffffffffu, acc[e], o);
    }

    if (lane == 0) {
        float* lp = logits_out ? (logits_out + t * E) : (g_logits_fb + t * E);
#pragma unroll
        for (int e = 0; e < E; e++) lp[e] = acc[e];

        // top-2 (strict > keeps lowest index on ties, matching jax top_k)
        int i1 = 0;
#pragma unroll
        for (int e = 1; e < E; e++) if (acc[e] > acc[i1]) i1 = e;
        int i2 = -1; float b = -3.4e38f;
#pragma unroll
        for (int e = 0; e < E; e++) if (e != i1 && acc[e] > b) { b = acc[e]; i2 = e; }

        // softmax Z cancels under top-k renormalization:
        float p2 = expf(acc[i2] - acc[i1]);
        float s  = 1.f + p2;
        float wv1 = 1.f / s;
        float wv2 = p2 / s;

        int q1 = atomicAdd(&g_count[i1], 1);
        g_tok[i1 * T + q1] = t; g_wt[i1 * T + q1] = wv1;
        int q2 = atomicAdd(&g_count[i2], 1);
        g_tok[i2 * T + q2] = t; g_wt[i2 * T + q2] = wv2;
    }
}

// ---------------- kernel 2: exclusive scan over 8 counters ----------------------
__global__ void scan_kernel() {
    int s = 0;
    for (int e = 0; e < E; e++) { g_base[e] = s; s += g_count[e]; }
}

// ---------------- kernel 3: fused up/gate GEMM + silu*mul -----------------------
// C[m, f] over expert e's token list: inter = silu(X w1^T) * (X w3^T)
// Tile: BM=128 tokens x BN=64 ff, BK=16, 256 threads, per-thread 8x4 x2 accums.
#define BM   128
#define BN   64
#define BK   16
#define XPAD 132
#define WPAD 68

__global__ __launch_bounds__(256, 2)
void upgate_kernel(const float* __restrict__ h,
                   const float* __restrict__ w1,
                   const float* __restrict__ w3) {
    int e   = blockIdx.z;
    int n_e = g_count[e];
    int m0  = blockIdx.y * BM;
    if (m0 >= n_e) return;
    int f0   = blockIdx.x * BN;
    int base = g_base[e];

    __shared__ float Xs[BK][XPAD];
    __shared__ float W1s[BK][WPAD];
    __shared__ float W3s[BK][WPAD];

    int tid = threadIdx.x;
    int kq  = (tid & 3) * 4;   // k offset of the float4 this thread loads
    int r0  = tid >> 2;        // 0..63

    int rA = m0 + r0, rB = m0 + r0 + 64;
    const float* xpA = (rA < n_e) ? h + (size_t)g_tok[e * T + rA] * Dm : nullptr;
    const float* xpB = (rB < n_e) ? h + (size_t)g_tok[e * T + rB] * Dm : nullptr;
    const float* w1p = w1 + ((size_t)e * FFm + f0 + r0) * Dm;
    const float* w3p = w3 + ((size_t)e * FFm + f0 + r0) * Dm;

    int tx = tid & 15;   // col group: cols tx*4
    int ty = tid >> 4;   // row group: rows ty*8

    float au[8][4], ag[8][4];
#pragma unroll
    for (int i = 0; i < 8; i++)
#pragma unroll
        for (int j = 0; j < 4; j++) { au[i][j] = 0.f; ag[i][j] = 0.f; }

    const float4 z4 = make_float4(0.f, 0.f, 0.f, 0.f);

    for (int k0 = 0; k0 < Dm; k0 += BK) {
        float4 xa = xpA ? *(const float4*)(xpA + k0 + kq) : z4;
        float4 xb = xpB ? *(const float4*)(xpB + k0 + kq) : z4;
        float4 wa = *(const float4*)(w1p + k0 + kq);
        float4 wb = *(const float4*)(w3p + k0 + kq);

        __syncthreads();
        Xs[kq + 0][r0] = xa.x; Xs[kq + 1][r0] = xa.y;
        Xs[kq + 2][r0] = xa.z; Xs[kq + 3][r0] = xa.w;
        Xs[kq + 0][r0 + 64] = xb.x; Xs[kq + 1][r0 + 64] = xb.y;
        Xs[kq + 2][r0 + 64] = xb.z; Xs[kq + 3][r0 + 64] = xb.w;
        W1s[kq + 0][r0] = wa.x; W1s[kq + 1][r0] = wa.y;
        W1s[kq + 2][r0] = wa.z; W1s[kq + 3][r0] = wa.w;
        W3s[kq + 0][r0] = wb.x; W3s[kq + 1][r0] = wb.y;
        W3s[kq + 2][r0] = wb.z; W3s[kq + 3][r0] = wb.w;
        __syncthreads();

#pragma unroll
        for (int kk = 0; kk < BK; kk++) {
            float4 a0 = *(const float4*)&Xs[kk][ty * 8];
            float4 a1 = *(const float4*)&Xs[kk][ty * 8 + 4];
            float4 bu = *(const float4*)&W1s[kk][tx * 4];
            float4 bg = *(const float4*)&W3s[kk][tx * 4];
            float a[8] = {a0.x, a0.y, a0.z, a0.w, a1.x, a1.y, a1.z, a1.w};
            float u[4] = {bu.x, bu.y, bu.z, bu.w};
            float g[4] = {bg.x, bg.y, bg.z, bg.w};
#pragma unroll
            for (int i = 0; i < 8; i++)
#pragma unroll
                for (int j = 0; j < 4; j++) {
                    au[i][j] += a[i] * u[j];
                    ag[i][j] += a[i] * g[j];
                }
        }
    }

#pragma unroll
    for (int i = 0; i < 8; i++) {
        int r = m0 + ty * 8 + i;
        if (r < n_e) {
            float* ip = &g_inter[(size_t)(base + r) * FFm + f0 + tx * 4];
#pragma unroll
            for (int j = 0; j < 4; j++) {
                float u = au[i][j];
                float sil = u / (1.f + expf(-u));
                ip[j] = sil * ag[i][j];
            }
        }
    }
}

// ---------------- kernel 4: down GEMM + weighted scatter-add --------------------
// out[tok, d] += wt * sum_f inter[slot, f] * w2[e, d, f]
// Tile: DBM=64 slots x DBN=128 d, DBK=16, 256 threads, per-thread 8x4 accums.
#define DBM 64
#define DBN 128
#define DBK 16

__global__ __launch_bounds__(256, 2)
void down_kernel(const float* __restrict__ w2, float* __restrict__ out) {
    int e   = blockIdx.z;
    int n_e = g_count[e];
    int m0  = blockIdx.y * DBM;
    if (m0 >= n_e) return;
    int d0   = blockIdx.x * DBN;
    int base = g_base[e];

    __shared__ float As[DBK][68];
    __shared__ float Ws[DBK][132];

    int tid = threadIdx.x;
    int kq  = (tid & 3) * 4;
    int r0  = tid >> 2;   // 0..63

    int rA = m0 + r0;
    const float* ap  = (rA < n_e) ? &g_inter[(size_t)(base + rA) * FFm] : nullptr;
    const float* wpA = w2 + ((size_t)e * Dm + d0 + r0) * FFm;
    const float* wpB = wpA + (size_t)64 * FFm;

    int tx = tid & 31;  // cols tx*4 of 128
    int ty = tid >> 5;  // rows ty*8 of 64

    float acc[8][4];
#pragma unroll
    for (int i = 0; i < 8; i++)
#pragma unroll
        for (int j = 0; j < 4; j++) acc[i][j] = 0.f;

    const float4 z4 = make_float4(0.f, 0.f, 0.f, 0.f);

    for (int k0 = 0; k0 < FFm; k0 += DBK) {
        float4 av = ap ? *(const float4*)(ap + k0 + kq) : z4;
        float4 wa = *(const float4*)(wpA + k0 + kq);
        float4 wb = *(const float4*)(wpB + k0 + kq);

        __syncthreads();
        As[kq + 0][r0] = av.x; As[kq + 1][r0] = av.y;
        As[kq + 2][r0] = av.z; As[kq + 3][r0] = av.w;
        Ws[kq + 0][r0] = wa.x; Ws[kq + 1][r0] = wa.y;
        Ws[kq + 2][r0] = wa.z; Ws[kq + 3][r0] = wa.w;
        Ws[kq + 0][r0 + 64] = wb.x; Ws[kq + 1][r0 + 64] = wb.y;
        Ws[kq + 2][r0 + 64] = wb.z; Ws[kq + 3][r0 + 64] = wb.w;
        __syncthreads();

#pragma unroll
        for (int kk = 0; kk < DBK; kk++) {
            float4 a0 = *(const float4*)&As[kk][ty * 8];
            float4 a1 = *(const float4*)&As[kk][ty * 8 + 4];
            float4 bw = *(const float4*)&Ws[kk][tx * 4];
            float a[8] = {a0.x, a0.y, a0.z, a0.w, a1.x, a1.y, a1.z, a1.w};
            float w[4] = {bw.x, bw.y, bw.z, bw.w};
#pragma unroll
            for (int i = 0; i < 8; i++)
#pragma unroll
                for (int j = 0; j < 4; j++) acc[i][j] += a[i] * w[j];
        }
    }

#pragma unroll
    for (int i = 0; i < 8; i++) {
        int r = m0 + ty * 8 + i;
        if (r < n_e) {
            int   tok = g_tok[e * T + r];
            float wgt = g_wt[e * T + r];
            float* op = out + (size_t)tok * Dm + d0 + tx * 4;
#pragma unroll
            for (int j = 0; j < 4; j++) atomicAdd(&op[j], wgt * acc[i][j]);
        }
    }
}

// ---------------- launch ---------------------------------------------------------
extern "C" void kernel_launch(void* const* d_in, const int* in_sizes, int n_in,
                              void* d_out, int out_size) {
    const float* h  = (const float*)d_in[0];   // [1,2048,1024]
    const float* gw = (const float*)d_in[1];   // [8,1024]
    const float* w1 = (const float*)d_in[2];   // [8,4096,1024]
    const float* w3 = (const float*)d_in[3];   // [8,4096,1024]
    const float* w2 = (const float*)d_in[4];   // [8,1024,4096]
    float* out = (float*)d_out;

    // zero output (poisoned); logits region is overwritten, out region accumulated
    cudaMemsetAsync(d_out, 0, (size_t)out_size * sizeof(float), 0);

    // logits go right after the [T, D] output if the buffer holds both
    float* logits = (out_size >= T * Dm + T * E) ? (out + (size_t)T * Dm) : nullptr;

    zero_counts_kernel<<<1, 32>>>();
    router_kernel<<<T / 8, 256>>>(h, gw, logits);   // 8 warps/block, 1 warp/token
    scan_kernel<<<1, 1>>>();

    dim3 gA(FFm / BN, T / BM, E);     // 64 x 16 x 8 (early-exit past n_e)
    upgate_kernel<<<gA, 256>>>(h, w1, w3);

    dim3 gB(Dm / DBN, T / DBM, E);    // 8 x 32 x 8
    down_kernel<<<gB, 256>>>(w2, out);
}

// round 5
// speedup vs baseline: 2.9698x; 2.9698x over previous
#include <cuda_runtime.h>
#include <math.h>
#include <stdint.h>

#define T    2048
#define Dm   1024
#define E    8
#define FFm  4096
#define NPAIR (T * 2)

// ---------------- scratch ----------------
__device__ int   g_count[E];
__device__ int   g_base[E];
__device__ int   g_tok[E * T];
__device__ float g_wt[E * T];
__device__ float g_inter[(size_t)NPAIR * FFm];   // 64 MB compact intermediate
__device__ float g_logits_fb[T * E];

// ---------------- helpers ----------------
__device__ __forceinline__ uint32_t smem_u32(const void* p) {
    uint32_t a;
    asm("{ .reg .u64 t; cvta.to.shared.u64 t, %1; cvt.u32.u64 %0, t; }" : "=r"(a) : "l"(p));
    return a;
}
__device__ __forceinline__ uint32_t f2tf(float x) {
    uint32_t u;
    asm("cvt.rna.tf32.f32 %0, %1;" : "=r"(u) : "f"(x));
    return u;
}
__device__ __forceinline__ void mma8(float* c, const uint32_t* a, const uint32_t* b) {
    asm volatile(
        "mma.sync.aligned.m16n8k8.row.col.f32.tf32.tf32.f32 "
        "{%0,%1,%2,%3}, {%4,%5,%6,%7}, {%8,%9}, {%0,%1,%2,%3};"
        : "+f"(c[0]), "+f"(c[1]), "+f"(c[2]), "+f"(c[3])
        : "r"(a[0]), "r"(a[1]), "r"(a[2]), "r"(a[3]), "r"(b[0]), "r"(b[1]));
}
#define CPA16(d, s) asm volatile("cp.async.cg.shared.global [%0], [%1], 16;" :: "r"(d), "l"(s))
#define CP_COMMIT() asm volatile("cp.async.commit_group;")

// smem geometry: padded row stride = 36 words (bank-conflict-free for frag pattern)
#define SA       36
#define STAGE_W  9216u           // words per stage (A 128*36 + B 128*36)
#define STAGE_B  36864u          // bytes per stage
#define SMEM_TOT 73728           // 2 stages

// ---------------- kernel 0: reset counters ----------------
__global__ void zero_counts_kernel() {
    if (threadIdx.x < E) g_count[threadIdx.x] = 0;
}

// ---------------- kernel 1: router ----------------
__global__ void router_kernel(const float* __restrict__ h,
                              const float* __restrict__ gw,
                              float* __restrict__ logits_out) {
    int warp = (blockIdx.x * blockDim.x + threadIdx.x) >> 5;
    int lane = threadIdx.x & 31;
    if (warp >= T) return;
    int t = warp;

    float acc[E];
#pragma unroll
    for (int e = 0; e < E; e++) acc[e] = 0.f;

    const float* hp = h + (size_t)t * Dm;
    for (int j = lane; j < Dm; j += 32) {
        float x = hp[j];
#pragma unroll
        for (int e = 0; e < E; e++) acc[e] += x * gw[e * Dm + j];
    }
#pragma unroll
    for (int e = 0; e < E; e++) {
#pragma unroll
        for (int o = 16; o; o >>= 1) acc[e] += __shfl_xor_sync(0xffffffffu, acc[e], o);
    }

    if (lane == 0) {
        float* lp = logits_out ? (logits_out + t * E) : (g_logits_fb + t * E);
#pragma unroll
        for (int e = 0; e < E; e++) lp[e] = acc[e];

        int i1 = 0;
#pragma unroll
        for (int e = 1; e < E; e++) if (acc[e] > acc[i1]) i1 = e;
        int i2 = -1; float b = -3.4e38f;
#pragma unroll
        for (int e = 0; e < E; e++) if (e != i1 && acc[e] > b) { b = acc[e]; i2 = e; }

        float p2 = expf(acc[i2] - acc[i1]);
        float s  = 1.f + p2;
        float wv1 = 1.f / s;
        float wv2 = p2 / s;

        int q1 = atomicAdd(&g_count[i1], 1);
        g_tok[i1 * T + q1] = t; g_wt[i1 * T + q1] = wv1;
        int q2 = atomicAdd(&g_count[i2], 1);
        g_tok[i2 * T + q2] = t; g_wt[i2 * T + q2] = wv2;
    }
}

// ---------------- kernel 2: scan ----------------
__global__ void scan_kernel() {
    int s = 0;
    for (int e = 0; e < E; e++) { g_base[e] = s; s += g_count[e]; }
}

// ---------------- kernel 3: upgate — mma.sync tf32 -------------------------------
// CTA: 128 tokens x 64 ff, dual outputs (w1 -> up, w3 -> gate).
// inter[slot, f] = silu(up) * gate
__global__ __launch_bounds__(256, 2)
void upgate_tc(const float* __restrict__ h,
               const float* __restrict__ w1,
               const float* __restrict__ w3) {
    int e   = blockIdx.z;
    int n_e = g_count[e];
    int m0  = blockIdx.x * 128;
    if (m0 >= n_e) return;
    int f0   = blockIdx.y * 64;
    int base = g_base[e];

    extern __shared__ float sm[];
    uint32_t smb = smem_u32(sm);
    int tid = threadIdx.x;

    // ---- loader setup: 8 x 16B cp.async per thread per chunk ----
    // A: 128 rows x 8 segs (32 floats); B1/B3: 64 rows x 8 segs each
    const float* srcA[4]; uint32_t dstA[4];
#pragma unroll
    for (int q = 0; q < 4; q++) {
        int seg = tid + q * 256, row = seg >> 3, sc = seg & 7;
        int ra = m0 + row; if (ra > n_e - 1) ra = n_e - 1;
        srcA[q] = h + (size_t)g_tok[e * T + ra] * Dm + sc * 4;
        dstA[q] = smb + (uint32_t)(row * SA + sc * 4) * 4u;
    }
    const float* srcB[4]; uint32_t dstB[4];
#pragma unroll
    for (int q = 0; q < 2; q++) {
        int seg = tid + q * 256, row = seg >> 3, sc = seg & 7;
        srcB[q]     = w1 + ((size_t)e * FFm + f0 + row) * Dm + sc * 4;
        dstB[q]     = smb + (uint32_t)(4608 + row * SA + sc * 4) * 4u;
        srcB[q + 2] = w3 + ((size_t)e * FFm + f0 + row) * Dm + sc * 4;
        dstB[q + 2] = smb + (uint32_t)(6912 + row * SA + sc * 4) * 4u;
    }

    int wid = tid >> 5, lane = tid & 31;
    int wm = wid & 3, wn = wid >> 2, g = lane >> 2, tg = lane & 3;

    float au[2][4][4], ag[2][4][4];
#pragma unroll
    for (int i = 0; i < 2; i++)
#pragma unroll
        for (int j = 0; j < 4; j++)
#pragma unroll
            for (int v = 0; v < 4; v++) { au[i][j][v] = 0.f; ag[i][j][v] = 0.f; }

    // prologue: chunk 0 -> stage 0
#pragma unroll
    for (int q = 0; q < 4; q++) CPA16(dstA[q], srcA[q]);
#pragma unroll
    for (int q = 0; q < 4; q++) CPA16(dstB[q], srcB[q]);
    CP_COMMIT();

    const int NCH = Dm / 32;   // 32
    for (int ch = 0; ch < NCH; ch++) {
        if (ch + 1 < NCH) {
            uint32_t so = ((uint32_t)(ch + 1) & 1u) * STAGE_B;
            int ko = (ch + 1) * 32;
#pragma unroll
            for (int q = 0; q < 4; q++) CPA16(dstA[q] + so, srcA[q] + ko);
#pragma unroll
            for (int q = 0; q < 4; q++) CPA16(dstB[q] + so, srcB[q] + ko);
            CP_COMMIT();
            asm volatile("cp.async.wait_group 1;");
        } else {
            asm volatile("cp.async.wait_group 0;");
        }
        __syncthreads();

        const float* As = sm + (ch & 1) * STAGE_W;
        const float* B1 = As + 4608;
        const float* B3 = As + 6912;
#pragma unroll
        for (int ks = 0; ks < 4; ks++) {
            int k = ks * 8;
            uint32_t a[2][4];
#pragma unroll
            for (int i = 0; i < 2; i++) {
                int r0 = wm * 32 + i * 16;
                a[i][0] = f2tf(As[(r0 + g) * SA + k + tg]);
                a[i][1] = f2tf(As[(r0 + 8 + g) * SA + k + tg]);
                a[i][2] = f2tf(As[(r0 + g) * SA + k + tg + 4]);
                a[i][3] = f2tf(As[(r0 + 8 + g) * SA + k + tg + 4]);
            }
            uint32_t b1[4][2], b3[4][2];
#pragma unroll
            for (int j = 0; j < 4; j++) {
                int n = wn * 32 + j * 8 + g;
                b1[j][0] = f2tf(B1[n * SA + k + tg]);
                b1[j][1] = f2tf(B1[n * SA + k + tg + 4]);
                b3[j][0] = f2tf(B3[n * SA + k + tg]);
                b3[j][1] = f2tf(B3[n * SA + k + tg + 4]);
            }
#pragma unroll
            for (int i = 0; i < 2; i++)
#pragma unroll
                for (int j = 0; j < 4; j++) {
                    mma8(au[i][j], a[i], b1[j]);
                    mma8(ag[i][j], a[i], b3[j]);
                }
        }
        __syncthreads();
    }

    // epilogue: silu(up)*gate -> g_inter
#pragma unroll
    for (int i = 0; i < 2; i++) {
        int r0 = m0 + wm * 32 + i * 16;
#pragma unroll
        for (int half = 0; half < 2; half++) {
            int rg = r0 + half * 8 + g;
            if (rg < n_e) {
                float* op = g_inter + (size_t)(base + rg) * FFm + f0 + wn * 32;
#pragma unroll
                for (int j = 0; j < 4; j++) {
                    float u0 = au[i][j][half * 2],     g0 = ag[i][j][half * 2];
                    float u1 = au[i][j][half * 2 + 1], g1 = ag[i][j][half * 2 + 1];
                    float2 v;
                    v.x = (u0 / (1.f + __expf(-u0))) * g0;
                    v.y = (u1 / (1.f + __expf(-u1))) * g1;
                    *(float2*)(op + j * 8 + 2 * tg) = v;
                }
            }
        }
    }
}

// ---------------- kernel 4: down — mma.sync tf32 + weighted scatter-add ----------
// CTA: 128 slots x 128 d.  out[tok, d] += wt * sum_f inter[slot, f] * w2[e][d, f]
__global__ __launch_bounds__(256, 2)
void down_tc(const float* __restrict__ w2, float* __restrict__ out) {
    int e   = blockIdx.z;
    int n_e = g_count[e];
    int m0  = blockIdx.x * 128;
    if (m0 >= n_e) return;
    int d0   = blockIdx.y * 128;
    int base = g_base[e];

    extern __shared__ float sm[];
    uint32_t smb = smem_u32(sm);
    int tid = threadIdx.x;

    const float* srcA[4]; uint32_t dstA[4];
#pragma unroll
    for (int q = 0; q < 4; q++) {
        int seg = tid + q * 256, row = seg >> 3, sc = seg & 7;
        int ra = m0 + row; if (ra > n_e - 1) ra = n_e - 1;
        srcA[q] = g_inter + (size_t)(base + ra) * FFm + sc * 4;
        dstA[q] = smb + (uint32_t)(row * SA + sc * 4) * 4u;
    }
    const float* srcB[4]; uint32_t dstB[4];
#pragma unroll
    for (int q = 0; q < 4; q++) {
        int seg = tid + q * 256, row = seg >> 3, sc = seg & 7;
        srcB[q] = w2 + ((size_t)e * Dm + d0 + row) * FFm + sc * 4;
        dstB[q] = smb + (uint32_t)(4608 + row * SA + sc * 4) * 4u;
    }

    int wid = tid >> 5, lane = tid & 31;
    int wm = wid & 3, wn = wid >> 2, g = lane >> 2, tg = lane & 3;

    float acc[2][8][4];
#pragma unroll
    for (int i = 0; i < 2; i++)
#pragma unroll
        for (int j = 0; j < 8; j++)
#pragma unroll
            for (int v = 0; v < 4; v++) acc[i][j][v] = 0.f;

#pragma unroll
    for (int q = 0; q < 4; q++) CPA16(dstA[q], srcA[q]);
#pragma unroll
    for (int q = 0; q < 4; q++) CPA16(dstB[q], srcB[q]);
    CP_COMMIT();

    const int NCH = FFm / 32;   // 128
    for (int ch = 0; ch < NCH; ch++) {
        if (ch + 1 < NCH) {
            uint32_t so = ((uint32_t)(ch + 1) & 1u) * STAGE_B;
            int ko = (ch + 1) * 32;
#pragma unroll
            for (int q = 0; q < 4; q++) CPA16(dstA[q] + so, srcA[q] + ko);
#pragma unroll
            for (int q = 0; q < 4; q++) CPA16(dstB[q] + so, srcB[q] + ko);
            CP_COMMIT();
            asm volatile("cp.async.wait_group 1;");
        } else {
            asm volatile("cp.async.wait_group 0;");
        }
        __syncthreads();

        const float* As = sm + (ch & 1) * STAGE_W;
        const float* Bs = As + 4608;
#pragma unroll
        for (int ks = 0; ks < 4; ks++) {
            int k = ks * 8;
            uint32_t a[2][4];
#pragma unroll
            for (int i = 0; i < 2; i++) {
                int r0 = wm * 32 + i * 16;
                a[i][0] = f2tf(As[(r0 + g) * SA + k + tg]);
                a[i][1] = f2tf(As[(r0 + 8 + g) * SA + k + tg]);
                a[i][2] = f2tf(As[(r0 + g) * SA + k + tg + 4]);
                a[i][3] = f2tf(As[(r0 + 8 + g) * SA + k + tg + 4]);
            }
#pragma unroll
            for (int j = 0; j < 8; j++) {
                int n = wn * 64 + j * 8 + g;
                uint32_t b[2];
                b[0] = f2tf(Bs[n * SA + k + tg]);
                b[1] = f2tf(Bs[n * SA + k + tg + 4]);
#pragma unroll
                for (int i = 0; i < 2; i++) mma8(acc[i][j], a[i], b);
            }
        }
        __syncthreads();
    }

    // epilogue: weighted atomic scatter
#pragma unroll
    for (int i = 0; i < 2; i++) {
        int r0 = m0 + wm * 32 + i * 16;
#pragma unroll
        for (int half = 0; half < 2; half++) {
            int rg = r0 + half * 8 + g;
            if (rg < n_e) {
                int   tok = g_tok[e * T + rg];
                float wgt = g_wt[e * T + rg];
                float* op = out + (size_t)tok * Dm + d0 + wn * 64;
#pragma unroll
                for (int j = 0; j < 8; j++) {
                    atomicAdd(op + j * 8 + 2 * tg,     wgt * acc[i][j][half * 2]);
                    atomicAdd(op + j * 8 + 2 * tg + 1, wgt * acc[i][j][half * 2 + 1]);
                }
            }
        }
    }
}

// ---------------- launch ----------------
extern "C" void kernel_launch(void* const* d_in, const int* in_sizes, int n_in,
                              void* d_out, int out_size) {
    const float* h  = (const float*)d_in[0];
    const float* gw = (const float*)d_in[1];
    const float* w1 = (const float*)d_in[2];
    const float* w3 = (const float*)d_in[3];
    const float* w2 = (const float*)d_in[4];
    float* out = (float*)d_out;

    cudaFuncSetAttribute(upgate_tc, cudaFuncAttributeMaxDynamicSharedMemorySize, SMEM_TOT);
    cudaFuncSetAttribute(down_tc,   cudaFuncAttributeMaxDynamicSharedMemorySize, SMEM_TOT);

    cudaMemsetAsync(d_out, 0, (size_t)out_size * sizeof(float), 0);

    float* logits = (out_size >= T * Dm + T * E) ? (out + (size_t)T * Dm) : nullptr;

    zero_counts_kernel<<<1, 32>>>();
    router_kernel<<<T / 8, 256>>>(h, gw, logits);
    scan_kernel<<<1, 1>>>();

    // x = m-tile fastest (same f-tile/d-tile CTAs share B in L2), y = n-tile, z = expert
    dim3 gA(16, FFm / 64, E);          // 16 x 64 x 8 (early-exit past n_e)
    upgate_tc<<<gA, 256, SMEM_TOT>>>(h, w1, w3);

    dim3 gB(16, Dm / 128, E);          // 16 x 8 x 8
    down_tc<<<gB, 256, SMEM_TOT>>>(w2, out);
}